// round 10
// baseline (speedup 1.0000x reference)
#include <cuda_runtime.h>
#include <cuda_bf16.h>
#include <math.h>
#include <stdint.h>

// ---------------- problem constants ----------------
#define BATCH 32
#define TLEN 64
#define SLEN 400
#define DIM 1024
#define VOCAB 32000
#define EXT 600
#define BT (BATCH * TLEN)      // 2048 rows
#define OUTW (VOCAB + EXT)     // 32600
#define PAD_IDX 1

// ---------------- GEMM tiling (bf16) ----------------
#define BM 128
#define BN 128
#define BK 64                       // 64 bf16 = 128B rows
#define STAGES 2
#define NCHUNK (DIM / BK)           // 16
#define A_TILE_BYTES (BM * 128)     // 16 KB
#define B_TILE_BYTES (BN * 128)     // 16 KB
#define STAGE_BYTES (A_TILE_BYTES + B_TILE_BYTES)  // 32 KB
#define SMEM_BYTES (STAGES * STAGE_BYTES)          // 64 KB -> 3 CTAs/SM

// ---------------- scratch (device globals; no allocation allowed) ----------
__device__ float g_pcopy[BT];
__device__ float g_rowsum[BT];
__device__ int   g_idx[SLEN * BATCH];
__device__ __nv_bfloat16 g_Wb[(size_t)VOCAB * DIM];   // bf16 W (64 MB)
__device__ __nv_bfloat16 g_Ab[(size_t)BT * DIM];      // bf16 hidden (4 MB)
__device__ __nv_bfloat16 g_E[(size_t)BT * VOCAB];     // bf16 exp(logits) (128 MB)

// ---------------- helpers ----------------
__device__ __forceinline__ uint32_t smem_u32(const void* p) {
    uint32_t a;
    asm("{ .reg .u64 t; cvta.to.shared.u64 t, %1; cvt.u32.u64 %0, t; }"
        : "=r"(a) : "l"(p));
    return a;
}

__device__ __forceinline__ void cpasync16(uint32_t dst, const void* src) {
    asm volatile("cp.async.cg.shared.global [%0], [%1], 16;"
                 :: "r"(dst), "l"(src) : "memory");
}

__device__ __forceinline__ void ldm_x4(uint32_t* r, uint32_t addr) {
    asm volatile("ldmatrix.sync.aligned.m8n8.x4.shared.b16 {%0,%1,%2,%3}, [%4];"
                 : "=r"(r[0]), "=r"(r[1]), "=r"(r[2]), "=r"(r[3]) : "r"(addr));
}

__device__ __forceinline__ void mma_bf16(float* c, const uint32_t* a,
                                         uint32_t b0, uint32_t b1) {
    asm volatile(
        "mma.sync.aligned.m16n8k16.row.col.f32.bf16.bf16.f32 "
        "{%0,%1,%2,%3}, {%4,%5,%6,%7}, {%8,%9}, {%0,%1,%2,%3};"
        : "+f"(c[0]), "+f"(c[1]), "+f"(c[2]), "+f"(c[3])
        : "r"(a[0]), "r"(a[1]), "r"(a[2]), "r"(a[3]), "r"(b0), "r"(b1));
}

// ---------------------------------------------------------------------------
// fp32 -> bf16 conversion (vectorized: float4 in, 8B out)
__global__ void cvt_bf16_kernel(const float4* __restrict__ src,
                                uint2* __restrict__ dst, int n4) {
    int stride = gridDim.x * blockDim.x;
    for (int i = blockIdx.x * blockDim.x + threadIdx.x; i < n4; i += stride) {
        float4 v = src[i];
        __nv_bfloat162 lo = __floats2bfloat162_rn(v.x, v.y);
        __nv_bfloat162 hi = __floats2bfloat162_rn(v.z, v.w);
        uint2 o;
        o.x = *(uint32_t*)&lo;
        o.y = *(uint32_t*)&hi;
        dst[i] = o;
    }
}

// ---------------------------------------------------------------------------
// p_copy + rowsum init + A->bf16 conversion (one block per row)
__global__ void pcopy_kernel(const float* __restrict__ hidden,
                             const float* __restrict__ Wc,
                             const float* __restrict__ bc) {
    int r = blockIdx.x;
    const float4* h4 = (const float4*)(hidden + (size_t)r * DIM);
    const float4* w4 = (const float4*)Wc;
    uint2* a8 = (uint2*)(g_Ab + (size_t)r * DIM);
    float s = 0.f;
    for (int k = threadIdx.x; k < DIM / 4; k += blockDim.x) {
        float4 hv = h4[k];
        float4 wv = w4[k];
        s += hv.x * wv.x + hv.y * wv.y + hv.z * wv.z + hv.w * wv.w;
        __nv_bfloat162 lo = __floats2bfloat162_rn(hv.x, hv.y);
        __nv_bfloat162 hi = __floats2bfloat162_rn(hv.z, hv.w);
        uint2 o;
        o.x = *(uint32_t*)&lo;
        o.y = *(uint32_t*)&hi;
        a8[k] = o;
    }
    __shared__ float red[32];
    for (int o = 16; o; o >>= 1) s += __shfl_down_sync(0xffffffffu, s, o);
    if ((threadIdx.x & 31) == 0) red[threadIdx.x >> 5] = s;
    __syncthreads();
    if (threadIdx.x < 32) {
        float t = (threadIdx.x < (blockDim.x >> 5)) ? red[threadIdx.x] : 0.f;
        for (int o = 16; o; o >>= 1) t += __shfl_down_sync(0xffffffffu, t, o);
        if (threadIdx.x == 0) {
            g_pcopy[r] = 1.f / (1.f + __expf(-(t + bc[0])));
            g_rowsum[r] = 0.f;
        }
    }
}

// vectorized argmax: one warp per (s, b) task, float4 loads
__global__ void argmax_kernel(const float* __restrict__ src_map) {
    int task = blockIdx.x * 8 + (threadIdx.x >> 5);
    if (task >= SLEN * BATCH) return;
    int lane = threadIdx.x & 31;
    const float4* p = (const float4*)(src_map + (size_t)task * EXT);
    float best = -INFINITY; int bi = EXT;
#pragma unroll
    for (int it = 0; it < 5; it++) {
        int f = it * 32 + lane;
        if (f < EXT / 4) {
            float4 v = p[f];
            int e = f * 4;
            if (v.x > best) { best = v.x; bi = e; }
            if (v.y > best) { best = v.y; bi = e + 1; }
            if (v.z > best) { best = v.z; bi = e + 2; }
            if (v.w > best) { best = v.w; bi = e + 3; }
        }
    }
    for (int off = 16; off; off >>= 1) {
        float ov = __shfl_down_sync(0xffffffffu, best, off);
        int   oi = __shfl_down_sync(0xffffffffu, bi, off);
        if (ov > best || (ov == best && oi < bi)) { best = ov; bi = oi; }
    }
    if (lane == 0) g_idx[task] = bi;
}

// ---------------------------------------------------------------------------
// bf16 mma.sync GEMM: g_E[m, n] = bf16(exp(A.W^T + b)) (PAD col -> 0),
// partial row sums into g_rowsum.  128x128 CTA, 4 warps, 3 CTAs/SM.
extern __shared__ char dyn_smem[];

__global__ __launch_bounds__(128, 3)
void gemm_tc_kernel(const __nv_bfloat16* __restrict__ A,   // (BT, DIM)
                    const __nv_bfloat16* __restrict__ W,   // (VOCAB, DIM)
                    const float* __restrict__ bias) {
    const uint32_t sbase = smem_u32(dyn_smem);
    const int tid  = threadIdx.x;
    const int wid  = tid >> 5;
    const int lane = tid & 31;
    const int warp_m = wid & 1;        // 0..1  (64-row slice of 128)
    const int warp_n = wid >> 1;       // 0..1  (64-col slice of 128)
    const int m0 = blockIdx.x * BM;
    const int n0 = blockIdx.y * BN;

    const __nv_bfloat16* Abase = A + (size_t)m0 * DIM;
    const __nv_bfloat16* Wbase = W + (size_t)n0 * DIM;

    auto load_stage = [&](int j) {
        uint32_t s = sbase + (uint32_t)(j % STAGES) * STAGE_BYTES;
        int k0 = j * BK;
#pragma unroll
        for (int i = 0; i < 16; i++) {
            int ch  = i * 128 + tid;              // 0..2047
            int row = ch >> 3;                    // 0..255
            int cc  = ch & 7;                     // 16B chunk in 128B row
            if (row < BM) {
                uint32_t off = (uint32_t)((cc * 16) ^ ((row & 7) << 4));
                cpasync16(s + (uint32_t)(row * 128) + off,
                          Abase + (size_t)row * DIM + k0 + cc * 8);
            } else {
                int br = row - BM;
                uint32_t off = (uint32_t)((cc * 16) ^ ((br & 7) << 4));
                cpasync16(s + A_TILE_BYTES + (uint32_t)(br * 128) + off,
                          Wbase + (size_t)br * DIM + k0 + cc * 8);
            }
        }
        asm volatile("cp.async.commit_group;" ::: "memory");
    };

    float acc[4][8][4];
#pragma unroll
    for (int i = 0; i < 4; i++)
#pragma unroll
        for (int j = 0; j < 8; j++)
#pragma unroll
            for (int q = 0; q < 4; q++) acc[i][j][q] = 0.f;

    const int tile = lane >> 3, tr = lane & 7;
    const int a_row0 = warp_m * 64 + (tile & 1) * 8 + tr;
    const int a_half = (tile >> 1) * 16;
    const int b_row0 = warp_n * 64 + (tile >> 1) * 8 + tr;
    const int b_half = (tile & 1) * 16;

    for (int j = 0; j < STAGES; j++) load_stage(j);

    for (int j = 0; j < NCHUNK; j++) {
        if (j < NCHUNK - 1)
            asm volatile("cp.async.wait_group %0;" :: "n"(STAGES - 1) : "memory");
        else
            asm volatile("cp.async.wait_group %0;" :: "n"(0) : "memory");
        __syncthreads();

        uint32_t sA = sbase + (uint32_t)(j % STAGES) * STAGE_BYTES;
        uint32_t sB = sA + A_TILE_BYTES;

#pragma unroll
        for (int ks = 0; ks < 4; ks++) {          // k16 steps within BK=64
            uint32_t a[4][4];
#pragma unroll
            for (int mt = 0; mt < 4; mt++) {
                int row = a_row0 + mt * 16;
                uint32_t col = (uint32_t)((ks * 32 + a_half) ^ ((row & 7) << 4));
                ldm_x4(a[mt], sA + (uint32_t)(row * 128) + col);
            }
            uint32_t bf[4][4];
#pragma unroll
            for (int bg = 0; bg < 4; bg++) {      // 4 n16 groups in 64
                int row = b_row0 + bg * 16;
                uint32_t col = (uint32_t)((ks * 32 + b_half) ^ ((row & 7) << 4));
                ldm_x4(bf[bg], sB + (uint32_t)(row * 128) + col);
            }
#pragma unroll
            for (int mt = 0; mt < 4; mt++)
#pragma unroll
                for (int bg = 0; bg < 4; bg++) {
                    mma_bf16(acc[mt][bg * 2 + 0], a[mt], bf[bg][0], bf[bg][1]);
                    mma_bf16(acc[mt][bg * 2 + 1], a[mt], bf[bg][2], bf[bg][3]);
                }
        }
        __syncthreads();
        if (j + STAGES < NCHUNK) load_stage(j + STAGES);
    }

    // ---- epilogue: bias + exp + bf16 store + row-sum ----
    const int g  = lane >> 2;          // 0..7
    const int q4 = lane & 3;
    float rs_lo[4], rs_hi[4];
#pragma unroll
    for (int mt = 0; mt < 4; mt++) { rs_lo[mt] = 0.f; rs_hi[mt] = 0.f; }

#pragma unroll
    for (int mt = 0; mt < 4; mt++) {
        int m_lo = m0 + warp_m * 64 + mt * 16 + g;
        int m_hi = m_lo + 8;
        uint32_t* row_lo = (uint32_t*)(g_E + (size_t)m_lo * VOCAB);
        uint32_t* row_hi = (uint32_t*)(g_E + (size_t)m_hi * VOCAB);
#pragma unroll
        for (int nt = 0; nt < 8; nt++) {
            int n = n0 + warp_n * 64 + nt * 8 + q4 * 2;
            float b0 = __ldg(&bias[n]);
            float b1 = __ldg(&bias[n + 1]);
            float e0 = __expf(acc[mt][nt][0] + b0);
            float e1 = __expf(acc[mt][nt][1] + b1);
            float e2 = __expf(acc[mt][nt][2] + b0);
            float e3 = __expf(acc[mt][nt][3] + b1);
            if (n == PAD_IDX)     { e0 = 0.f; e2 = 0.f; }
            if (n + 1 == PAD_IDX) { e1 = 0.f; e3 = 0.f; }
            __nv_bfloat162 p_lo = __floats2bfloat162_rn(e0, e1);
            __nv_bfloat162 p_hi = __floats2bfloat162_rn(e2, e3);
            row_lo[n >> 1] = *(uint32_t*)&p_lo;
            row_hi[n >> 1] = *(uint32_t*)&p_hi;
            rs_lo[mt] += e0 + e1;
            rs_hi[mt] += e2 + e3;
        }
    }
#pragma unroll
    for (int mt = 0; mt < 4; mt++) {
        float lo = rs_lo[mt], hi = rs_hi[mt];
        lo += __shfl_xor_sync(0xffffffffu, lo, 1);
        lo += __shfl_xor_sync(0xffffffffu, lo, 2);
        hi += __shfl_xor_sync(0xffffffffu, hi, 1);
        hi += __shfl_xor_sync(0xffffffffu, hi, 2);
        if (q4 == 0) {
            int m_lo = m0 + warp_m * 64 + mt * 16 + g;
            atomicAdd(&g_rowsum[m_lo], lo);
            atomicAdd(&g_rowsum[m_lo + 8], hi);
        }
    }
}

// ---------------------------------------------------------------------------
// Fused finish: normalize bf16 exp -> fp32 out, and build copy-prob bins.
__global__ __launch_bounds__(512)
void finish_kernel(const float* __restrict__ attn,
                   float* __restrict__ out) {
    int r = blockIdx.x;
    int b = r % BATCH;               // rows are tlen-major: r = t*BATCH + b
    float pc = g_pcopy[r];
    float s = (1.f - pc) / g_rowsum[r];

    __shared__ float bins[EXT];
    for (int c = threadIdx.x; c < EXT; c += blockDim.x) bins[c] = 0.f;
    __syncthreads();
    const float* arow = attn + (size_t)r * SLEN;
    for (int si = threadIdx.x; si < SLEN; si += blockDim.x)
        atomicAdd(&bins[g_idx[si * BATCH + b]], arow[si]);

    // normalize vocab part: read bf16x4, write fp32x4
    const uint2* erow = (const uint2*)(g_E + (size_t)r * VOCAB);
    float4* row = (float4*)(out + (size_t)r * OUTW);
    for (int i = threadIdx.x; i < VOCAB / 4; i += blockDim.x) {
        uint2 pk = erow[i];
        __nv_bfloat162 lo = *(__nv_bfloat162*)&pk.x;
        __nv_bfloat162 hi = *(__nv_bfloat162*)&pk.y;
        float4 v;
        v.x = __bfloat162float(lo.x) * s;
        v.y = __bfloat162float(lo.y) * s;
        v.z = __bfloat162float(hi.x) * s;
        v.w = __bfloat162float(hi.y) * s;
        row[i] = v;
    }
    __syncthreads();
    float* orow = out + (size_t)r * OUTW + VOCAB;
    for (int c = threadIdx.x; c < EXT; c += blockDim.x)
        orow[c] = bins[c] * pc;
}

// ---------------------------------------------------------------------------
extern "C" void kernel_launch(void* const* d_in, const int* in_sizes, int n_in,
                              void* d_out, int out_size) {
    const float* hidden = (const float*)d_in[0];
    const float* attn   = (const float*)d_in[1];
    const float* srcmap = (const float*)d_in[2];
    const float* W      = (const float*)d_in[3];
    const float* b      = (const float*)d_in[4];
    const float* Wc     = (const float*)d_in[5];
    const float* bc     = (const float*)d_in[6];
    float* out = (float*)d_out;

    cudaFuncSetAttribute(gemm_tc_kernel,
                         cudaFuncAttributeMaxDynamicSharedMemorySize, SMEM_BYTES);

    __nv_bfloat16 *Wbv, *Abv;
    cudaGetSymbolAddress((void**)&Wbv, g_Wb);
    cudaGetSymbolAddress((void**)&Abv, g_Ab);

    cvt_bf16_kernel<<<2048, 256>>>((const float4*)W, (uint2*)Wbv,
                                   (int)((size_t)VOCAB * DIM / 4));
    pcopy_kernel<<<BT, 256>>>(hidden, Wc, bc);
    argmax_kernel<<<(SLEN * BATCH + 7) / 8, 256>>>(srcmap);

    dim3 grid(BT / BM, VOCAB / BN);   // (16, 250): waves share W slices in L2
    gemm_tc_kernel<<<grid, 128, SMEM_BYTES>>>(Abv, Wbv, b);

    finish_kernel<<<BT, 512>>>(attn, out);
}

// round 11
// speedup vs baseline: 1.1196x; 1.1196x over previous
#include <cuda_runtime.h>
#include <cuda_bf16.h>
#include <math.h>
#include <stdint.h>

// ---------------- problem constants ----------------
#define BATCH 32
#define TLEN 64
#define SLEN 400
#define DIM 1024
#define VOCAB 32000
#define EXT 600
#define BT (BATCH * TLEN)      // 2048 rows
#define OUTW (VOCAB + EXT)     // 32600
#define PAD_IDX 1

// ---------------- GEMM tiling (bf16) ----------------
#define BM 128
#define BN 128
#define BK 64                       // 64 bf16 = 128B rows
#define STAGES 3
#define NCHUNK (DIM / BK)           // 16
#define A_TILE_BYTES (BM * 128)     // 16 KB
#define B_TILE_BYTES (BN * 128)     // 16 KB
#define STAGE_BYTES (A_TILE_BYTES + B_TILE_BYTES)  // 32 KB
#define SMEM_BYTES (STAGES * STAGE_BYTES)          // 96 KB -> 2 CTAs/SM

// ---------------- scratch (device globals; no allocation allowed) ----------
__device__ float g_pcopy[BT];
__device__ float g_rowsum[BT];
__device__ int   g_idx[SLEN * BATCH];
__device__ __nv_bfloat16 g_Wb[(size_t)VOCAB * DIM];   // bf16 W (64 MB)
__device__ __nv_bfloat16 g_Ab[(size_t)BT * DIM];      // bf16 hidden (4 MB)
__device__ __nv_bfloat16 g_E[(size_t)BT * VOCAB];     // bf16 exp(logits) (128 MB)

// ---------------- helpers ----------------
__device__ __forceinline__ uint32_t smem_u32(const void* p) {
    uint32_t a;
    asm("{ .reg .u64 t; cvta.to.shared.u64 t, %1; cvt.u32.u64 %0, t; }"
        : "=r"(a) : "l"(p));
    return a;
}

__device__ __forceinline__ void cpasync16(uint32_t dst, const void* src) {
    asm volatile("cp.async.cg.shared.global [%0], [%1], 16;"
                 :: "r"(dst), "l"(src) : "memory");
}

__device__ __forceinline__ void ldm_x4(uint32_t* r, uint32_t addr) {
    asm volatile("ldmatrix.sync.aligned.m8n8.x4.shared.b16 {%0,%1,%2,%3}, [%4];"
                 : "=r"(r[0]), "=r"(r[1]), "=r"(r[2]), "=r"(r[3]) : "r"(addr));
}

__device__ __forceinline__ void mma_bf16(float* c, const uint32_t* a,
                                         uint32_t b0, uint32_t b1) {
    asm volatile(
        "mma.sync.aligned.m16n8k16.row.col.f32.bf16.bf16.f32 "
        "{%0,%1,%2,%3}, {%4,%5,%6,%7}, {%8,%9}, {%0,%1,%2,%3};"
        : "+f"(c[0]), "+f"(c[1]), "+f"(c[2]), "+f"(c[3])
        : "r"(a[0]), "r"(a[1]), "r"(a[2]), "r"(a[3]), "r"(b0), "r"(b1));
}

// ---------------------------------------------------------------------------
// fp32 -> bf16 conversion (vectorized: float4 in, 8B out)
__global__ void cvt_bf16_kernel(const float4* __restrict__ src,
                                uint2* __restrict__ dst, int n4) {
    int stride = gridDim.x * blockDim.x;
    for (int i = blockIdx.x * blockDim.x + threadIdx.x; i < n4; i += stride) {
        float4 v = src[i];
        __nv_bfloat162 lo = __floats2bfloat162_rn(v.x, v.y);
        __nv_bfloat162 hi = __floats2bfloat162_rn(v.z, v.w);
        uint2 o;
        o.x = *(uint32_t*)&lo;
        o.y = *(uint32_t*)&hi;
        dst[i] = o;
    }
}

// ---------------------------------------------------------------------------
// p_copy + rowsum init + A->bf16 conversion (one block per row)
__global__ void pcopy_kernel(const float* __restrict__ hidden,
                             const float* __restrict__ Wc,
                             const float* __restrict__ bc) {
    int r = blockIdx.x;
    const float4* h4 = (const float4*)(hidden + (size_t)r * DIM);
    const float4* w4 = (const float4*)Wc;
    uint2* a8 = (uint2*)(g_Ab + (size_t)r * DIM);
    float s = 0.f;
    for (int k = threadIdx.x; k < DIM / 4; k += blockDim.x) {
        float4 hv = h4[k];
        float4 wv = w4[k];
        s += hv.x * wv.x + hv.y * wv.y + hv.z * wv.z + hv.w * wv.w;
        __nv_bfloat162 lo = __floats2bfloat162_rn(hv.x, hv.y);
        __nv_bfloat162 hi = __floats2bfloat162_rn(hv.z, hv.w);
        uint2 o;
        o.x = *(uint32_t*)&lo;
        o.y = *(uint32_t*)&hi;
        a8[k] = o;
    }
    __shared__ float red[32];
    for (int o = 16; o; o >>= 1) s += __shfl_down_sync(0xffffffffu, s, o);
    if ((threadIdx.x & 31) == 0) red[threadIdx.x >> 5] = s;
    __syncthreads();
    if (threadIdx.x < 32) {
        float t = (threadIdx.x < (blockDim.x >> 5)) ? red[threadIdx.x] : 0.f;
        for (int o = 16; o; o >>= 1) t += __shfl_down_sync(0xffffffffu, t, o);
        if (threadIdx.x == 0) {
            g_pcopy[r] = 1.f / (1.f + __expf(-(t + bc[0])));
            g_rowsum[r] = 0.f;
        }
    }
}

// vectorized argmax: one warp per (s, b) task, float4 loads
__global__ void argmax_kernel(const float* __restrict__ src_map) {
    int task = blockIdx.x * 8 + (threadIdx.x >> 5);
    if (task >= SLEN * BATCH) return;
    int lane = threadIdx.x & 31;
    const float4* p = (const float4*)(src_map + (size_t)task * EXT);
    float best = -INFINITY; int bi = EXT;
#pragma unroll
    for (int it = 0; it < 5; it++) {
        int f = it * 32 + lane;
        if (f < EXT / 4) {
            float4 v = p[f];
            int e = f * 4;
            if (v.x > best) { best = v.x; bi = e; }
            if (v.y > best) { best = v.y; bi = e + 1; }
            if (v.z > best) { best = v.z; bi = e + 2; }
            if (v.w > best) { best = v.w; bi = e + 3; }
        }
    }
    for (int off = 16; off; off >>= 1) {
        float ov = __shfl_down_sync(0xffffffffu, best, off);
        int   oi = __shfl_down_sync(0xffffffffu, bi, off);
        if (ov > best || (ov == best && oi < bi)) { best = ov; bi = oi; }
    }
    if (lane == 0) g_idx[task] = bi;
}

// ---------------------------------------------------------------------------
// bf16 mma.sync GEMM: g_E[m, n] = bf16(exp(A.W^T + b)) (PAD col -> 0),
// partial row sums into g_rowsum.
// 128x128 CTA, 8 warps (32x64 warp tiles), 2 CTAs/SM, ~110 regs/thread.
extern __shared__ char dyn_smem[];

__global__ __launch_bounds__(256, 2)
void gemm_tc_kernel(const __nv_bfloat16* __restrict__ A,   // (BT, DIM)
                    const __nv_bfloat16* __restrict__ W,   // (VOCAB, DIM)
                    const float* __restrict__ bias) {
    const uint32_t sbase = smem_u32(dyn_smem);
    const int tid  = threadIdx.x;
    const int wid  = tid >> 5;
    const int lane = tid & 31;
    const int warp_m = wid & 3;        // 0..3  (32-row slice of 128)
    const int warp_n = wid >> 2;       // 0..1  (64-col slice of 128)
    const int m0 = blockIdx.x * BM;
    const int n0 = blockIdx.y * BN;

    const __nv_bfloat16* Abase = A + (size_t)m0 * DIM;
    const __nv_bfloat16* Wbase = W + (size_t)n0 * DIM;

    // loader: 256 rows x 8 chunks(16B) = 2048 chunks / 256 thr = 8 each
    auto load_stage = [&](int j) {
        uint32_t s = sbase + (uint32_t)(j % STAGES) * STAGE_BYTES;
        int k0 = j * BK;
#pragma unroll
        for (int i = 0; i < 8; i++) {
            int ch  = i * 256 + tid;              // 0..2047
            int row = ch >> 3;                    // 0..255
            int cc  = ch & 7;                     // 16B chunk in 128B row
            if (row < BM) {
                uint32_t off = (uint32_t)((cc * 16) ^ ((row & 7) << 4));
                cpasync16(s + (uint32_t)(row * 128) + off,
                          Abase + (size_t)row * DIM + k0 + cc * 8);
            } else {
                int br = row - BM;
                uint32_t off = (uint32_t)((cc * 16) ^ ((br & 7) << 4));
                cpasync16(s + A_TILE_BYTES + (uint32_t)(br * 128) + off,
                          Wbase + (size_t)br * DIM + k0 + cc * 8);
            }
        }
        asm volatile("cp.async.commit_group;" ::: "memory");
    };

    float acc[2][8][4];
#pragma unroll
    for (int i = 0; i < 2; i++)
#pragma unroll
        for (int j = 0; j < 8; j++)
#pragma unroll
            for (int q = 0; q < 4; q++) acc[i][j][q] = 0.f;

    const int tile = lane >> 3, tr = lane & 7;
    const int a_row0 = warp_m * 32 + (tile & 1) * 8 + tr;
    const int a_half = (tile >> 1) * 16;
    const int b_row0 = warp_n * 64 + (tile >> 1) * 8 + tr;
    const int b_half = (tile & 1) * 16;

    for (int j = 0; j < STAGES; j++) load_stage(j);

    for (int j = 0; j < NCHUNK; j++) {
        if (j < NCHUNK - 2)
            asm volatile("cp.async.wait_group %0;" :: "n"(STAGES - 1) : "memory");
        else if (j == NCHUNK - 2)
            asm volatile("cp.async.wait_group %0;" :: "n"(1) : "memory");
        else
            asm volatile("cp.async.wait_group %0;" :: "n"(0) : "memory");
        __syncthreads();

        uint32_t sA = sbase + (uint32_t)(j % STAGES) * STAGE_BYTES;
        uint32_t sB = sA + A_TILE_BYTES;

#pragma unroll
        for (int ks = 0; ks < 4; ks++) {          // k16 steps within BK=64
            uint32_t a[2][4];
#pragma unroll
            for (int mt = 0; mt < 2; mt++) {
                int row = a_row0 + mt * 16;
                uint32_t col = (uint32_t)((ks * 32 + a_half) ^ ((row & 7) << 4));
                ldm_x4(a[mt], sA + (uint32_t)(row * 128) + col);
            }
            uint32_t bf[4][4];
#pragma unroll
            for (int bg = 0; bg < 4; bg++) {      // 4 n16 groups in 64
                int row = b_row0 + bg * 16;
                uint32_t col = (uint32_t)((ks * 32 + b_half) ^ ((row & 7) << 4));
                ldm_x4(bf[bg], sB + (uint32_t)(row * 128) + col);
            }
#pragma unroll
            for (int mt = 0; mt < 2; mt++)
#pragma unroll
                for (int bg = 0; bg < 4; bg++) {
                    mma_bf16(acc[mt][bg * 2 + 0], a[mt], bf[bg][0], bf[bg][1]);
                    mma_bf16(acc[mt][bg * 2 + 1], a[mt], bf[bg][2], bf[bg][3]);
                }
        }
        __syncthreads();
        if (j + STAGES < NCHUNK) load_stage(j + STAGES);
    }

    // ---- epilogue: bias + exp + bf16 store + row-sum ----
    const int g  = lane >> 2;          // 0..7
    const int q4 = lane & 3;
    float rs_lo[2], rs_hi[2];
#pragma unroll
    for (int mt = 0; mt < 2; mt++) { rs_lo[mt] = 0.f; rs_hi[mt] = 0.f; }

#pragma unroll
    for (int mt = 0; mt < 2; mt++) {
        int m_lo = m0 + warp_m * 32 + mt * 16 + g;
        int m_hi = m_lo + 8;
        uint32_t* row_lo = (uint32_t*)(g_E + (size_t)m_lo * VOCAB);
        uint32_t* row_hi = (uint32_t*)(g_E + (size_t)m_hi * VOCAB);
#pragma unroll
        for (int nt = 0; nt < 8; nt++) {
            int n = n0 + warp_n * 64 + nt * 8 + q4 * 2;
            float b0 = __ldg(&bias[n]);
            float b1 = __ldg(&bias[n + 1]);
            float e0 = __expf(acc[mt][nt][0] + b0);
            float e1 = __expf(acc[mt][nt][1] + b1);
            float e2 = __expf(acc[mt][nt][2] + b0);
            float e3 = __expf(acc[mt][nt][3] + b1);
            if (n == PAD_IDX)     { e0 = 0.f; e2 = 0.f; }
            if (n + 1 == PAD_IDX) { e1 = 0.f; e3 = 0.f; }
            __nv_bfloat162 p_lo = __floats2bfloat162_rn(e0, e1);
            __nv_bfloat162 p_hi = __floats2bfloat162_rn(e2, e3);
            row_lo[n >> 1] = *(uint32_t*)&p_lo;
            row_hi[n >> 1] = *(uint32_t*)&p_hi;
            rs_lo[mt] += e0 + e1;
            rs_hi[mt] += e2 + e3;
        }
    }
#pragma unroll
    for (int mt = 0; mt < 2; mt++) {
        float lo = rs_lo[mt], hi = rs_hi[mt];
        lo += __shfl_xor_sync(0xffffffffu, lo, 1);
        lo += __shfl_xor_sync(0xffffffffu, lo, 2);
        hi += __shfl_xor_sync(0xffffffffu, hi, 1);
        hi += __shfl_xor_sync(0xffffffffu, hi, 2);
        if (q4 == 0) {
            int m_lo = m0 + warp_m * 32 + mt * 16 + g;
            atomicAdd(&g_rowsum[m_lo], lo);
            atomicAdd(&g_rowsum[m_lo + 8], hi);
        }
    }
}

// ---------------------------------------------------------------------------
// Fused finish: normalize bf16 exp -> fp32 out, and build copy-prob bins.
__global__ __launch_bounds__(512)
void finish_kernel(const float* __restrict__ attn,
                   float* __restrict__ out) {
    int r = blockIdx.x;
    int b = r % BATCH;               // rows are tlen-major: r = t*BATCH + b
    float pc = g_pcopy[r];
    float s = (1.f - pc) / g_rowsum[r];

    __shared__ float bins[EXT];
    for (int c = threadIdx.x; c < EXT; c += blockDim.x) bins[c] = 0.f;
    __syncthreads();
    const float* arow = attn + (size_t)r * SLEN;
    for (int si = threadIdx.x; si < SLEN; si += blockDim.x)
        atomicAdd(&bins[g_idx[si * BATCH + b]], arow[si]);

    // normalize vocab part: read bf16x4, write fp32x4
    const uint2* erow = (const uint2*)(g_E + (size_t)r * VOCAB);
    float4* row = (float4*)(out + (size_t)r * OUTW);
    for (int i = threadIdx.x; i < VOCAB / 4; i += blockDim.x) {
        uint2 pk = erow[i];
        __nv_bfloat162 lo = *(__nv_bfloat162*)&pk.x;
        __nv_bfloat162 hi = *(__nv_bfloat162*)&pk.y;
        float4 v;
        v.x = __bfloat162float(lo.x) * s;
        v.y = __bfloat162float(lo.y) * s;
        v.z = __bfloat162float(hi.x) * s;
        v.w = __bfloat162float(hi.y) * s;
        row[i] = v;
    }
    __syncthreads();
    float* orow = out + (size_t)r * OUTW + VOCAB;
    for (int c = threadIdx.x; c < EXT; c += blockDim.x)
        orow[c] = bins[c] * pc;
}

// ---------------------------------------------------------------------------
extern "C" void kernel_launch(void* const* d_in, const int* in_sizes, int n_in,
                              void* d_out, int out_size) {
    const float* hidden = (const float*)d_in[0];
    const float* attn   = (const float*)d_in[1];
    const float* srcmap = (const float*)d_in[2];
    const float* W      = (const float*)d_in[3];
    const float* b      = (const float*)d_in[4];
    const float* Wc     = (const float*)d_in[5];
    const float* bc     = (const float*)d_in[6];
    float* out = (float*)d_out;

    cudaFuncSetAttribute(gemm_tc_kernel,
                         cudaFuncAttributeMaxDynamicSharedMemorySize, SMEM_BYTES);

    __nv_bfloat16 *Wbv, *Abv;
    cudaGetSymbolAddress((void**)&Wbv, g_Wb);
    cudaGetSymbolAddress((void**)&Abv, g_Ab);

    cvt_bf16_kernel<<<2048, 256>>>((const float4*)W, (uint2*)Wbv,
                                   (int)((size_t)VOCAB * DIM / 4));
    pcopy_kernel<<<BT, 256>>>(hidden, Wc, bc);
    argmax_kernel<<<(SLEN * BATCH + 7) / 8, 256>>>(srcmap);

    dim3 grid(BT / BM, VOCAB / BN);   // (16, 250): waves share W slices in L2
    gemm_tc_kernel<<<grid, 256, SMEM_BYTES>>>(Abv, Wbv, b);

    finish_kernel<<<BT, 512>>>(attn, out);
}

// round 13
// speedup vs baseline: 1.1723x; 1.0471x over previous
#include <cuda_runtime.h>
#include <cuda_bf16.h>
#include <math.h>
#include <stdint.h>

// ---------------- problem constants ----------------
#define BATCH 32
#define TLEN 64
#define SLEN 400
#define DIM 1024
#define VOCAB 32000
#define EXT 600
#define BT (BATCH * TLEN)      // 2048 rows
#define OUTW (VOCAB + EXT)     // 32600
#define PAD_IDX 1

// ---------------- GEMM tiling (bf16) ----------------
#define BM 128
#define BN 128
#define BK 64                       // 64 bf16 = 128B rows
#define STAGES 3
#define NCHUNK (DIM / BK)           // 16
#define A_TILE_BYTES (BM * 128)     // 16 KB
#define B_TILE_BYTES (BN * 128)     // 16 KB
#define STAGE_BYTES (A_TILE_BYTES + B_TILE_BYTES)  // 32 KB
#define SMEM_BYTES (STAGES * STAGE_BYTES)          // 96 KB -> 2 CTAs/SM

// prep kernel block ranges
#define PREP_CVT_BLOCKS 2048
#define PREP_PCOPY_BLOCKS BT            // 2048
#define PREP_ARGMAX_BLOCKS ((SLEN * BATCH + 7) / 8)   // 1600 blocks = 12800 warps
#define PREP_BLOCKS (PREP_CVT_BLOCKS + PREP_PCOPY_BLOCKS + PREP_ARGMAX_BLOCKS)

// ---------------- scratch (device globals; no allocation allowed) ----------
__device__ float g_pcopy[BT];
__device__ float g_rowsum[BT];
__device__ int   g_idx[SLEN * BATCH];
__device__ __nv_bfloat16 g_Wb[(size_t)VOCAB * DIM];   // bf16 W (64 MB)
__device__ __nv_bfloat16 g_Ab[(size_t)BT * DIM];      // bf16 hidden (4 MB)
__device__ __nv_bfloat16 g_E[(size_t)BT * VOCAB];     // bf16 exp(logits) (128 MB)

// ---------------- helpers ----------------
__device__ __forceinline__ uint32_t smem_u32(const void* p) {
    uint32_t a;
    asm("{ .reg .u64 t; cvta.to.shared.u64 t, %1; cvt.u32.u64 %0, t; }"
        : "=r"(a) : "l"(p));
    return a;
}

__device__ __forceinline__ void cpasync16(uint32_t dst, const void* src) {
    asm volatile("cp.async.cg.shared.global [%0], [%1], 16;"
                 :: "r"(dst), "l"(src) : "memory");
}

__device__ __forceinline__ void ldm_x4(uint32_t* r, uint32_t addr) {
    asm volatile("ldmatrix.sync.aligned.m8n8.x4.shared.b16 {%0,%1,%2,%3}, [%4];"
                 : "=r"(r[0]), "=r"(r[1]), "=r"(r[2]), "=r"(r[3]) : "r"(addr));
}

__device__ __forceinline__ void mma_bf16(float* c, const uint32_t* a,
                                         uint32_t b0, uint32_t b1) {
    asm volatile(
        "mma.sync.aligned.m16n8k16.row.col.f32.bf16.bf16.f32 "
        "{%0,%1,%2,%3}, {%4,%5,%6,%7}, {%8,%9}, {%0,%1,%2,%3};"
        : "+f"(c[0]), "+f"(c[1]), "+f"(c[2]), "+f"(c[3])
        : "r"(a[0]), "r"(a[1]), "r"(a[2]), "r"(a[3]), "r"(b0), "r"(b1));
}

// ---------------------------------------------------------------------------
// Fused prep: W->bf16 cvt  |  pcopy + rowsum init + A->bf16  |  argmax.
// Dispatch on blockIdx.x ranges; all 256-thread blocks.
__global__ __launch_bounds__(256)
void prep_kernel(const float* __restrict__ W,
                 const float* __restrict__ hidden,
                 const float* __restrict__ Wc,
                 const float* __restrict__ bc,
                 const float* __restrict__ src_map) {
    int blk = blockIdx.x;

    if (blk < PREP_CVT_BLOCKS) {
        // ---- W fp32 -> bf16, grid-stride over 8.2M float4 groups ----
        const float4* src = (const float4*)W;
        uint2* dst = (uint2*)g_Wb;
        const int n4 = (int)((size_t)VOCAB * DIM / 4);
        const int stride = PREP_CVT_BLOCKS * 256;
        for (int i = blk * 256 + threadIdx.x; i < n4; i += stride) {
            float4 v = src[i];
            __nv_bfloat162 lo = __floats2bfloat162_rn(v.x, v.y);
            __nv_bfloat162 hi = __floats2bfloat162_rn(v.z, v.w);
            uint2 o;
            o.x = *(uint32_t*)&lo;
            o.y = *(uint32_t*)&hi;
            dst[i] = o;
        }
        return;
    }
    blk -= PREP_CVT_BLOCKS;

    if (blk < PREP_PCOPY_BLOCKS) {
        // ---- pcopy + rowsum init + A->bf16 (one block per row) ----
        int r = blk;
        const float4* h4 = (const float4*)(hidden + (size_t)r * DIM);
        const float4* w4 = (const float4*)Wc;
        uint2* a8 = (uint2*)(g_Ab + (size_t)r * DIM);
        float s = 0.f;
        for (int k = threadIdx.x; k < DIM / 4; k += blockDim.x) {
            float4 hv = h4[k];
            float4 wv = w4[k];
            s += hv.x * wv.x + hv.y * wv.y + hv.z * wv.z + hv.w * wv.w;
            __nv_bfloat162 lo = __floats2bfloat162_rn(hv.x, hv.y);
            __nv_bfloat162 hi = __floats2bfloat162_rn(hv.z, hv.w);
            uint2 o;
            o.x = *(uint32_t*)&lo;
            o.y = *(uint32_t*)&hi;
            a8[k] = o;
        }
        __shared__ float red[32];
        for (int o = 16; o; o >>= 1) s += __shfl_down_sync(0xffffffffu, s, o);
        if ((threadIdx.x & 31) == 0) red[threadIdx.x >> 5] = s;
        __syncthreads();
        if (threadIdx.x < 32) {
            float t = (threadIdx.x < (blockDim.x >> 5)) ? red[threadIdx.x] : 0.f;
            for (int o = 16; o; o >>= 1) t += __shfl_down_sync(0xffffffffu, t, o);
            if (threadIdx.x == 0) {
                g_pcopy[r] = 1.f / (1.f + __expf(-(t + bc[0])));
                g_rowsum[r] = 0.f;
            }
        }
        return;
    }
    blk -= PREP_PCOPY_BLOCKS;

    // ---- argmax: one warp per (s, b) task, float4 loads ----
    int task = blk * 8 + (threadIdx.x >> 5);
    if (task >= SLEN * BATCH) return;
    int lane = threadIdx.x & 31;
    const float4* p = (const float4*)(src_map + (size_t)task * EXT);
    float best = -INFINITY; int bi = EXT;
#pragma unroll
    for (int it = 0; it < 5; it++) {
        int f = it * 32 + lane;
        if (f < EXT / 4) {
            float4 v = p[f];
            int e = f * 4;
            if (v.x > best) { best = v.x; bi = e; }
            if (v.y > best) { best = v.y; bi = e + 1; }
            if (v.z > best) { best = v.z; bi = e + 2; }
            if (v.w > best) { best = v.w; bi = e + 3; }
        }
    }
    for (int off = 16; off; off >>= 1) {
        float ov = __shfl_down_sync(0xffffffffu, best, off);
        int   oi = __shfl_down_sync(0xffffffffu, bi, off);
        if (ov > best || (ov == best && oi < bi)) { best = ov; bi = oi; }
    }
    if (lane == 0) g_idx[task] = bi;
}

// ---------------------------------------------------------------------------
// bf16 mma.sync GEMM: g_E[m, n] = bf16(exp(A.W^T + b)) (PAD col -> 0),
// partial row sums into g_rowsum.  128x128 CTA, 4 warps (64x64 warp tiles),
// 2 CTAs/SM, ~252 regs/thread.  (R9 config — best measured.)
extern __shared__ char dyn_smem[];

__global__ __launch_bounds__(128, 2)
void gemm_tc_kernel(const __nv_bfloat16* __restrict__ A,   // (BT, DIM)
                    const __nv_bfloat16* __restrict__ W,   // (VOCAB, DIM)
                    const float* __restrict__ bias) {
    const uint32_t sbase = smem_u32(dyn_smem);
    const int tid  = threadIdx.x;
    const int wid  = tid >> 5;
    const int lane = tid & 31;
    const int warp_m = wid & 1;        // 0..1  (64-row slice of 128)
    const int warp_n = wid >> 1;       // 0..1  (64-col slice of 128)
    const int m0 = blockIdx.x * BM;
    const int n0 = blockIdx.y * BN;

    const __nv_bfloat16* Abase = A + (size_t)m0 * DIM;
    const __nv_bfloat16* Wbase = W + (size_t)n0 * DIM;

    auto load_stage = [&](int j) {
        uint32_t s = sbase + (uint32_t)(j % STAGES) * STAGE_BYTES;
        int k0 = j * BK;
#pragma unroll
        for (int i = 0; i < 16; i++) {
            int ch  = i * 128 + tid;              // 0..2047
            int row = ch >> 3;                    // 0..255
            int cc  = ch & 7;                     // 16B chunk in 128B row
            if (row < BM) {
                uint32_t off = (uint32_t)((cc * 16) ^ ((row & 7) << 4));
                cpasync16(s + (uint32_t)(row * 128) + off,
                          Abase + (size_t)row * DIM + k0 + cc * 8);
            } else {
                int br = row - BM;
                uint32_t off = (uint32_t)((cc * 16) ^ ((br & 7) << 4));
                cpasync16(s + A_TILE_BYTES + (uint32_t)(br * 128) + off,
                          Wbase + (size_t)br * DIM + k0 + cc * 8);
            }
        }
        asm volatile("cp.async.commit_group;" ::: "memory");
    };

    float acc[4][8][4];
#pragma unroll
    for (int i = 0; i < 4; i++)
#pragma unroll
        for (int j = 0; j < 8; j++)
#pragma unroll
            for (int q = 0; q < 4; q++) acc[i][j][q] = 0.f;

    const int tile = lane >> 3, tr = lane & 7;
    const int a_row0 = warp_m * 64 + (tile & 1) * 8 + tr;
    const int a_half = (tile >> 1) * 16;
    const int b_row0 = warp_n * 64 + (tile >> 1) * 8 + tr;
    const int b_half = (tile & 1) * 16;

    for (int j = 0; j < STAGES; j++) load_stage(j);

    for (int j = 0; j < NCHUNK; j++) {
        if (j < NCHUNK - 2)
            asm volatile("cp.async.wait_group %0;" :: "n"(STAGES - 1) : "memory");
        else if (j == NCHUNK - 2)
            asm volatile("cp.async.wait_group %0;" :: "n"(1) : "memory");
        else
            asm volatile("cp.async.wait_group %0;" :: "n"(0) : "memory");
        __syncthreads();

        uint32_t sA = sbase + (uint32_t)(j % STAGES) * STAGE_BYTES;
        uint32_t sB = sA + A_TILE_BYTES;

#pragma unroll
        for (int ks = 0; ks < 4; ks++) {          // k16 steps within BK=64
            uint32_t a[4][4];
#pragma unroll
            for (int mt = 0; mt < 4; mt++) {
                int row = a_row0 + mt * 16;
                uint32_t col = (uint32_t)((ks * 32 + a_half) ^ ((row & 7) << 4));
                ldm_x4(a[mt], sA + (uint32_t)(row * 128) + col);
            }
            uint32_t bf[4][4];
#pragma unroll
            for (int bg = 0; bg < 4; bg++) {      // 4 n16 groups in 64
                int row = b_row0 + bg * 16;
                uint32_t col = (uint32_t)((ks * 32 + b_half) ^ ((row & 7) << 4));
                ldm_x4(bf[bg], sB + (uint32_t)(row * 128) + col);
            }
#pragma unroll
            for (int mt = 0; mt < 4; mt++)
#pragma unroll
                for (int bg = 0; bg < 4; bg++) {
                    mma_bf16(acc[mt][bg * 2 + 0], a[mt], bf[bg][0], bf[bg][1]);
                    mma_bf16(acc[mt][bg * 2 + 1], a[mt], bf[bg][2], bf[bg][3]);
                }
        }
        __syncthreads();
        if (j + STAGES < NCHUNK) load_stage(j + STAGES);
    }

    // ---- epilogue: bias + exp + bf16 store + row-sum ----
    const int g  = lane >> 2;          // 0..7
    const int q4 = lane & 3;
    float rs_lo[4], rs_hi[4];
#pragma unroll
    for (int mt = 0; mt < 4; mt++) { rs_lo[mt] = 0.f; rs_hi[mt] = 0.f; }

#pragma unroll
    for (int mt = 0; mt < 4; mt++) {
        int m_lo = m0 + warp_m * 64 + mt * 16 + g;
        int m_hi = m_lo + 8;
        uint32_t* row_lo = (uint32_t*)(g_E + (size_t)m_lo * VOCAB);
        uint32_t* row_hi = (uint32_t*)(g_E + (size_t)m_hi * VOCAB);
#pragma unroll
        for (int nt = 0; nt < 8; nt++) {
            int n = n0 + warp_n * 64 + nt * 8 + q4 * 2;
            float b0 = __ldg(&bias[n]);
            float b1 = __ldg(&bias[n + 1]);
            float e0 = __expf(acc[mt][nt][0] + b0);
            float e1 = __expf(acc[mt][nt][1] + b1);
            float e2 = __expf(acc[mt][nt][2] + b0);
            float e3 = __expf(acc[mt][nt][3] + b1);
            if (n == PAD_IDX)     { e0 = 0.f; e2 = 0.f; }
            if (n + 1 == PAD_IDX) { e1 = 0.f; e3 = 0.f; }
            __nv_bfloat162 p_lo = __floats2bfloat162_rn(e0, e1);
            __nv_bfloat162 p_hi = __floats2bfloat162_rn(e2, e3);
            row_lo[n >> 1] = *(uint32_t*)&p_lo;
            row_hi[n >> 1] = *(uint32_t*)&p_hi;
            rs_lo[mt] += e0 + e1;
            rs_hi[mt] += e2 + e3;
        }
    }
#pragma unroll
    for (int mt = 0; mt < 4; mt++) {
        float lo = rs_lo[mt], hi = rs_hi[mt];
        lo += __shfl_xor_sync(0xffffffffu, lo, 1);
        lo += __shfl_xor_sync(0xffffffffu, lo, 2);
        hi += __shfl_xor_sync(0xffffffffu, hi, 1);
        hi += __shfl_xor_sync(0xffffffffu, hi, 2);
        if (q4 == 0) {
            int m_lo = m0 + warp_m * 64 + mt * 16 + g;
            atomicAdd(&g_rowsum[m_lo], lo);
            atomicAdd(&g_rowsum[m_lo + 8], hi);
        }
    }
}

// ---------------------------------------------------------------------------
// Fused finish: normalize bf16 exp -> fp32 out, and build copy-prob bins.
__global__ __launch_bounds__(512)
void finish_kernel(const float* __restrict__ attn,
                   float* __restrict__ out) {
    int r = blockIdx.x;
    int b = r % BATCH;               // rows are tlen-major: r = t*BATCH + b
    float pc = g_pcopy[r];
    float s = (1.f - pc) / g_rowsum[r];

    __shared__ float bins[EXT];
    for (int c = threadIdx.x; c < EXT; c += blockDim.x) bins[c] = 0.f;
    __syncthreads();
    const float* arow = attn + (size_t)r * SLEN;
    for (int si = threadIdx.x; si < SLEN; si += blockDim.x)
        atomicAdd(&bins[g_idx[si * BATCH + b]], arow[si]);

    // normalize vocab part: read bf16x4, write fp32x4
    const uint2* erow = (const uint2*)(g_E + (size_t)r * VOCAB);
    float4* row = (float4*)(out + (size_t)r * OUTW);
    for (int i = threadIdx.x; i < VOCAB / 4; i += blockDim.x) {
        uint2 pk = erow[i];
        __nv_bfloat162 lo = *(__nv_bfloat162*)&pk.x;
        __nv_bfloat162 hi = *(__nv_bfloat162*)&pk.y;
        float4 v;
        v.x = __bfloat162float(lo.x) * s;
        v.y = __bfloat162float(lo.y) * s;
        v.z = __bfloat162float(hi.x) * s;
        v.w = __bfloat162float(hi.y) * s;
        row[i] = v;
    }
    __syncthreads();
    float* orow = out + (size_t)r * OUTW + VOCAB;
    for (int c = threadIdx.x; c < EXT; c += blockDim.x)
        orow[c] = bins[c] * pc;
}

// ---------------------------------------------------------------------------
extern "C" void kernel_launch(void* const* d_in, const int* in_sizes, int n_in,
                              void* d_out, int out_size) {
    const float* hidden = (const float*)d_in[0];
    const float* attn   = (const float*)d_in[1];
    const float* srcmap = (const float*)d_in[2];
    const float* W      = (const float*)d_in[3];
    const float* b      = (const float*)d_in[4];
    const float* Wc     = (const float*)d_in[5];
    const float* bc     = (const float*)d_in[6];
    float* out = (float*)d_out;

    cudaFuncSetAttribute(gemm_tc_kernel,
                         cudaFuncAttributeMaxDynamicSharedMemorySize, SMEM_BYTES);

    __nv_bfloat16 *Wbv, *Abv;
    cudaGetSymbolAddress((void**)&Wbv, g_Wb);
    cudaGetSymbolAddress((void**)&Abv, g_Ab);

    prep_kernel<<<PREP_BLOCKS, 256>>>(W, hidden, Wc, bc, srcmap);

    dim3 grid(BT / BM, VOCAB / BN);   // (16, 250): waves share W slices in L2
    gemm_tc_kernel<<<grid, 128, SMEM_BYTES>>>(Abv, Wbv, b);

    finish_kernel<<<BT, 512>>>(attn, out);
}

// round 14
// speedup vs baseline: 1.1832x; 1.0092x over previous
#include <cuda_runtime.h>
#include <cuda_bf16.h>
#include <math.h>
#include <stdint.h>

// ---------------- problem constants ----------------
#define BATCH 32
#define TLEN 64
#define SLEN 400
#define DIM 1024
#define VOCAB 32000
#define EXT 600
#define BT (BATCH * TLEN)      // 2048 rows
#define OUTW (VOCAB + EXT)     // 32600
#define PAD_IDX 1

// ---------------- GEMM tiling (bf16) ----------------
#define BM 128
#define BN 128
#define BK 64                       // 64 bf16 = 128B rows
#define STAGES 3
#define NCHUNK (DIM / BK)           // 16
#define A_TILE_BYTES (BM * 128)     // 16 KB
#define B_TILE_BYTES (BN * 128)     // 16 KB
#define STAGE_BYTES (A_TILE_BYTES + B_TILE_BYTES)  // 32 KB
#define SMEM_BYTES (STAGES * STAGE_BYTES)          // 96 KB -> 2 CTAs/SM

#define GEMM_BLOCKS ((BT / BM) * (VOCAB / BN))     // 4000
#define AMX_TASKS (SLEN * BATCH)                   // 12800
#define AMX_BLOCKS 400                             // 4 warps x 8 tasks each
#define TOTAL_GEMM_GRID (GEMM_BLOCKS + AMX_BLOCKS)

// prep kernel block ranges (W cvt + pcopy only; argmax rides the gemm tail)
#define PREP_CVT_BLOCKS 2048
#define PREP_PCOPY_BLOCKS BT            // 2048
#define PREP_BLOCKS (PREP_CVT_BLOCKS + PREP_PCOPY_BLOCKS)

// ---------------- scratch (device globals; no allocation allowed) ----------
__device__ float g_pcopy[BT];
__device__ float g_rowsum[BT];
__device__ int   g_idx[AMX_TASKS];
__device__ __nv_bfloat16 g_Wb[(size_t)VOCAB * DIM];   // bf16 W (64 MB)
__device__ __nv_bfloat16 g_Ab[(size_t)BT * DIM];      // bf16 hidden (4 MB)
__device__ __nv_bfloat16 g_E[(size_t)BT * VOCAB];     // bf16 exp(logits) (128 MB)

// ---------------- helpers ----------------
__device__ __forceinline__ uint32_t smem_u32(const void* p) {
    uint32_t a;
    asm("{ .reg .u64 t; cvta.to.shared.u64 t, %1; cvt.u32.u64 %0, t; }"
        : "=r"(a) : "l"(p));
    return a;
}

__device__ __forceinline__ void cpasync16(uint32_t dst, const void* src) {
    asm volatile("cp.async.cg.shared.global [%0], [%1], 16;"
                 :: "r"(dst), "l"(src) : "memory");
}

__device__ __forceinline__ void ldm_x4(uint32_t* r, uint32_t addr) {
    asm volatile("ldmatrix.sync.aligned.m8n8.x4.shared.b16 {%0,%1,%2,%3}, [%4];"
                 : "=r"(r[0]), "=r"(r[1]), "=r"(r[2]), "=r"(r[3]) : "r"(addr));
}

__device__ __forceinline__ void mma_bf16(float* c, const uint32_t* a,
                                         uint32_t b0, uint32_t b1) {
    asm volatile(
        "mma.sync.aligned.m16n8k16.row.col.f32.bf16.bf16.f32 "
        "{%0,%1,%2,%3}, {%4,%5,%6,%7}, {%8,%9}, {%0,%1,%2,%3};"
        : "+f"(c[0]), "+f"(c[1]), "+f"(c[2]), "+f"(c[3])
        : "r"(a[0]), "r"(a[1]), "r"(a[2]), "r"(a[3]), "r"(b0), "r"(b1));
}

// ---------------------------------------------------------------------------
// Fused prep: W->bf16 cvt  |  pcopy + rowsum init + A->bf16.
__global__ __launch_bounds__(256)
void prep_kernel(const float* __restrict__ W,
                 const float* __restrict__ hidden,
                 const float* __restrict__ Wc,
                 const float* __restrict__ bc) {
    int blk = blockIdx.x;

    if (blk < PREP_CVT_BLOCKS) {
        // ---- W fp32 -> bf16, grid-stride over 8.2M float4 groups ----
        const float4* src = (const float4*)W;
        uint2* dst = (uint2*)g_Wb;
        const int n4 = (int)((size_t)VOCAB * DIM / 4);
        const int stride = PREP_CVT_BLOCKS * 256;
        for (int i = blk * 256 + threadIdx.x; i < n4; i += stride) {
            float4 v = src[i];
            __nv_bfloat162 lo = __floats2bfloat162_rn(v.x, v.y);
            __nv_bfloat162 hi = __floats2bfloat162_rn(v.z, v.w);
            uint2 o;
            o.x = *(uint32_t*)&lo;
            o.y = *(uint32_t*)&hi;
            dst[i] = o;
        }
        return;
    }
    blk -= PREP_CVT_BLOCKS;

    // ---- pcopy + rowsum init + A->bf16 (one block per row) ----
    int r = blk;
    const float4* h4 = (const float4*)(hidden + (size_t)r * DIM);
    const float4* w4 = (const float4*)Wc;
    uint2* a8 = (uint2*)(g_Ab + (size_t)r * DIM);
    float s = 0.f;
    for (int k = threadIdx.x; k < DIM / 4; k += blockDim.x) {
        float4 hv = h4[k];
        float4 wv = w4[k];
        s += hv.x * wv.x + hv.y * wv.y + hv.z * wv.z + hv.w * wv.w;
        __nv_bfloat162 lo = __floats2bfloat162_rn(hv.x, hv.y);
        __nv_bfloat162 hi = __floats2bfloat162_rn(hv.z, hv.w);
        uint2 o;
        o.x = *(uint32_t*)&lo;
        o.y = *(uint32_t*)&hi;
        a8[k] = o;
    }
    __shared__ float red[32];
    for (int o = 16; o; o >>= 1) s += __shfl_down_sync(0xffffffffu, s, o);
    if ((threadIdx.x & 31) == 0) red[threadIdx.x >> 5] = s;
    __syncthreads();
    if (threadIdx.x < 32) {
        float t = (threadIdx.x < (blockDim.x >> 5)) ? red[threadIdx.x] : 0.f;
        for (int o = 16; o; o >>= 1) t += __shfl_down_sync(0xffffffffu, t, o);
        if (threadIdx.x == 0) {
            g_pcopy[r] = 1.f / (1.f + __expf(-(t + bc[0])));
            g_rowsum[r] = 0.f;
        }
    }
}

// ---------------------------------------------------------------------------
// bf16 mma.sync GEMM (R9 config) + argmax tail blocks.
// bid < GEMM_BLOCKS: 128x128 GEMM tile -> g_E = bf16(exp(A.W^T + b)),
//   partial row sums into g_rowsum.  4 warps (64x64 warp tiles), 2 CTAs/SM.
// bid >= GEMM_BLOCKS: argmax blocks (4 warps x 8 tasks) ride the gemm tail.
extern __shared__ char dyn_smem[];

__global__ __launch_bounds__(128, 2)
void gemm_tc_kernel(const __nv_bfloat16* __restrict__ A,   // (BT, DIM)
                    const __nv_bfloat16* __restrict__ W,   // (VOCAB, DIM)
                    const float* __restrict__ bias,
                    const float* __restrict__ src_map) {
    const int tid  = threadIdx.x;
    const int wid  = tid >> 5;
    const int lane = tid & 31;

    if (blockIdx.x >= GEMM_BLOCKS) {
        // ---- argmax: each warp handles 8 (s, b) tasks, float4 loads ----
        int ab = blockIdx.x - GEMM_BLOCKS;       // 0..AMX_BLOCKS-1
#pragma unroll
        for (int t8 = 0; t8 < 8; t8++) {
            int task = (ab * 4 + wid) * 8 + t8;  // 400*4 warps x 8
            if (task >= AMX_TASKS) break;
            const float4* p = (const float4*)(src_map + (size_t)task * EXT);
            float best = -INFINITY; int bi = EXT;
#pragma unroll
            for (int it = 0; it < 5; it++) {
                int f = it * 32 + lane;
                if (f < EXT / 4) {
                    float4 v = p[f];
                    int e = f * 4;
                    if (v.x > best) { best = v.x; bi = e; }
                    if (v.y > best) { best = v.y; bi = e + 1; }
                    if (v.z > best) { best = v.z; bi = e + 2; }
                    if (v.w > best) { best = v.w; bi = e + 3; }
                }
            }
            for (int off = 16; off; off >>= 1) {
                float ov = __shfl_down_sync(0xffffffffu, best, off);
                int   oi = __shfl_down_sync(0xffffffffu, bi, off);
                if (ov > best || (ov == best && oi < bi)) { best = ov; bi = oi; }
            }
            if (lane == 0) g_idx[task] = bi;
        }
        return;
    }

    // ---- GEMM path ----
    const uint32_t sbase = smem_u32(dyn_smem);
    const int warp_m = wid & 1;        // 0..1  (64-row slice of 128)
    const int warp_n = wid >> 1;       // 0..1  (64-col slice of 128)
    const int m0 = (blockIdx.x % (BT / BM)) * BM;      // wave order same as 2D
    const int n0 = (blockIdx.x / (BT / BM)) * BN;

    const __nv_bfloat16* Abase = A + (size_t)m0 * DIM;
    const __nv_bfloat16* Wbase = W + (size_t)n0 * DIM;

    auto load_stage = [&](int j) {
        uint32_t s = sbase + (uint32_t)(j % STAGES) * STAGE_BYTES;
        int k0 = j * BK;
#pragma unroll
        for (int i = 0; i < 16; i++) {
            int ch  = i * 128 + tid;              // 0..2047
            int row = ch >> 3;                    // 0..255
            int cc  = ch & 7;                     // 16B chunk in 128B row
            if (row < BM) {
                uint32_t off = (uint32_t)((cc * 16) ^ ((row & 7) << 4));
                cpasync16(s + (uint32_t)(row * 128) + off,
                          Abase + (size_t)row * DIM + k0 + cc * 8);
            } else {
                int br = row - BM;
                uint32_t off = (uint32_t)((cc * 16) ^ ((br & 7) << 4));
                cpasync16(s + A_TILE_BYTES + (uint32_t)(br * 128) + off,
                          Wbase + (size_t)br * DIM + k0 + cc * 8);
            }
        }
        asm volatile("cp.async.commit_group;" ::: "memory");
    };

    float acc[4][8][4];
#pragma unroll
    for (int i = 0; i < 4; i++)
#pragma unroll
        for (int j = 0; j < 8; j++)
#pragma unroll
            for (int q = 0; q < 4; q++) acc[i][j][q] = 0.f;

    const int tile = lane >> 3, tr = lane & 7;
    const int a_row0 = warp_m * 64 + (tile & 1) * 8 + tr;
    const int a_half = (tile >> 1) * 16;
    const int b_row0 = warp_n * 64 + (tile >> 1) * 8 + tr;
    const int b_half = (tile & 1) * 16;

    for (int j = 0; j < STAGES; j++) load_stage(j);

    for (int j = 0; j < NCHUNK; j++) {
        if (j < NCHUNK - 2)
            asm volatile("cp.async.wait_group %0;" :: "n"(STAGES - 1) : "memory");
        else if (j == NCHUNK - 2)
            asm volatile("cp.async.wait_group %0;" :: "n"(1) : "memory");
        else
            asm volatile("cp.async.wait_group %0;" :: "n"(0) : "memory");
        __syncthreads();

        uint32_t sA = sbase + (uint32_t)(j % STAGES) * STAGE_BYTES;
        uint32_t sB = sA + A_TILE_BYTES;

#pragma unroll
        for (int ks = 0; ks < 4; ks++) {          // k16 steps within BK=64
            uint32_t a[4][4];
#pragma unroll
            for (int mt = 0; mt < 4; mt++) {
                int row = a_row0 + mt * 16;
                uint32_t col = (uint32_t)((ks * 32 + a_half) ^ ((row & 7) << 4));
                ldm_x4(a[mt], sA + (uint32_t)(row * 128) + col);
            }
            uint32_t bf[4][4];
#pragma unroll
            for (int bg = 0; bg < 4; bg++) {      // 4 n16 groups in 64
                int row = b_row0 + bg * 16;
                uint32_t col = (uint32_t)((ks * 32 + b_half) ^ ((row & 7) << 4));
                ldm_x4(bf[bg], sB + (uint32_t)(row * 128) + col);
            }
#pragma unroll
            for (int mt = 0; mt < 4; mt++)
#pragma unroll
                for (int bg = 0; bg < 4; bg++) {
                    mma_bf16(acc[mt][bg * 2 + 0], a[mt], bf[bg][0], bf[bg][1]);
                    mma_bf16(acc[mt][bg * 2 + 1], a[mt], bf[bg][2], bf[bg][3]);
                }
        }
        __syncthreads();
        if (j + STAGES < NCHUNK) load_stage(j + STAGES);
    }

    // ---- epilogue: bias + exp + bf16 store + row-sum ----
    const int g  = lane >> 2;          // 0..7
    const int q4 = lane & 3;
    float rs_lo[4], rs_hi[4];
#pragma unroll
    for (int mt = 0; mt < 4; mt++) { rs_lo[mt] = 0.f; rs_hi[mt] = 0.f; }

#pragma unroll
    for (int mt = 0; mt < 4; mt++) {
        int m_lo = m0 + warp_m * 64 + mt * 16 + g;
        int m_hi = m_lo + 8;
        uint32_t* row_lo = (uint32_t*)(g_E + (size_t)m_lo * VOCAB);
        uint32_t* row_hi = (uint32_t*)(g_E + (size_t)m_hi * VOCAB);
#pragma unroll
        for (int nt = 0; nt < 8; nt++) {
            int n = n0 + warp_n * 64 + nt * 8 + q4 * 2;
            float b0 = __ldg(&bias[n]);
            float b1 = __ldg(&bias[n + 1]);
            float e0 = __expf(acc[mt][nt][0] + b0);
            float e1 = __expf(acc[mt][nt][1] + b1);
            float e2 = __expf(acc[mt][nt][2] + b0);
            float e3 = __expf(acc[mt][nt][3] + b1);
            if (n == PAD_IDX)     { e0 = 0.f; e2 = 0.f; }
            if (n + 1 == PAD_IDX) { e1 = 0.f; e3 = 0.f; }
            __nv_bfloat162 p_lo = __floats2bfloat162_rn(e0, e1);
            __nv_bfloat162 p_hi = __floats2bfloat162_rn(e2, e3);
            row_lo[n >> 1] = *(uint32_t*)&p_lo;
            row_hi[n >> 1] = *(uint32_t*)&p_hi;
            rs_lo[mt] += e0 + e1;
            rs_hi[mt] += e2 + e3;
        }
    }
#pragma unroll
    for (int mt = 0; mt < 4; mt++) {
        float lo = rs_lo[mt], hi = rs_hi[mt];
        lo += __shfl_xor_sync(0xffffffffu, lo, 1);
        lo += __shfl_xor_sync(0xffffffffu, lo, 2);
        hi += __shfl_xor_sync(0xffffffffu, hi, 1);
        hi += __shfl_xor_sync(0xffffffffu, hi, 2);
        if (q4 == 0) {
            int m_lo = m0 + warp_m * 64 + mt * 16 + g;
            atomicAdd(&g_rowsum[m_lo], lo);
            atomicAdd(&g_rowsum[m_lo + 8], hi);
        }
    }
}

// ---------------------------------------------------------------------------
// Fused finish: normalize bf16 exp -> fp32 out, and build copy-prob bins.
__global__ __launch_bounds__(512)
void finish_kernel(const float* __restrict__ attn,
                   float* __restrict__ out) {
    int r = blockIdx.x;
    int b = r % BATCH;               // rows are tlen-major: r = t*BATCH + b
    float pc = g_pcopy[r];
    float s = (1.f - pc) / g_rowsum[r];

    __shared__ float bins[EXT];
    for (int c = threadIdx.x; c < EXT; c += blockDim.x) bins[c] = 0.f;
    __syncthreads();
    const float* arow = attn + (size_t)r * SLEN;
    for (int si = threadIdx.x; si < SLEN; si += blockDim.x)
        atomicAdd(&bins[g_idx[si * BATCH + b]], arow[si]);

    // normalize vocab part: read bf16x4, write fp32x4
    const uint2* erow = (const uint2*)(g_E + (size_t)r * VOCAB);
    float4* row = (float4*)(out + (size_t)r * OUTW);
    for (int i = threadIdx.x; i < VOCAB / 4; i += blockDim.x) {
        uint2 pk = erow[i];
        __nv_bfloat162 lo = *(__nv_bfloat162*)&pk.x;
        __nv_bfloat162 hi = *(__nv_bfloat162*)&pk.y;
        float4 v;
        v.x = __bfloat162float(lo.x) * s;
        v.y = __bfloat162float(lo.y) * s;
        v.z = __bfloat162float(hi.x) * s;
        v.w = __bfloat162float(hi.y) * s;
        row[i] = v;
    }
    __syncthreads();
    float* orow = out + (size_t)r * OUTW + VOCAB;
    for (int c = threadIdx.x; c < EXT; c += blockDim.x)
        orow[c] = bins[c] * pc;
}

// ---------------------------------------------------------------------------
extern "C" void kernel_launch(void* const* d_in, const int* in_sizes, int n_in,
                              void* d_out, int out_size) {
    const float* hidden = (const float*)d_in[0];
    const float* attn   = (const float*)d_in[1];
    const float* srcmap = (const float*)d_in[2];
    const float* W      = (const float*)d_in[3];
    const float* b      = (const float*)d_in[4];
    const float* Wc     = (const float*)d_in[5];
    const float* bc     = (const float*)d_in[6];
    float* out = (float*)d_out;

    cudaFuncSetAttribute(gemm_tc_kernel,
                         cudaFuncAttributeMaxDynamicSharedMemorySize, SMEM_BYTES);

    __nv_bfloat16 *Wbv, *Abv;
    cudaGetSymbolAddress((void**)&Wbv, g_Wb);
    cudaGetSymbolAddress((void**)&Abv, g_Ab);

    prep_kernel<<<PREP_BLOCKS, 256>>>(W, hidden, Wc, bc);

    gemm_tc_kernel<<<TOTAL_GEMM_GRID, 128, SMEM_BYTES>>>(Abv, Wbv, b, srcmap);

    finish_kernel<<<BT, 512>>>(attn, out);
}